// round 4
// baseline (speedup 1.0000x reference)
#include <cuda_runtime.h>
#include <cuda_bf16.h>
#include <cstdint>
#include <cstddef>

#define T_LEN 4096
#define EMBD  300
#define HID   512
#define KTAG  20
#define START_TAG 18
#define STOP_TAG  19
#define NEGV  (-10000.0f)
#define CHUNK 16
#define NCHUNK (T_LEN / CHUNK)   // 256

// ---------------- scratch (static device globals; no allocation) ----------------
__device__ float              g_xproj[2][T_LEN][4 * HID];  // 64 MB
__device__ float              g_hs[2][T_LEN][HID];         // 16 MB
__device__ float              g_feats[T_LEN][KTAG];
__device__ unsigned long long g_hpair[2][2][HID];          // [dir][parity][h]: {tag|bits}
__device__ float              g_tree[2][NCHUNK][KTAG][KTAG];

__device__ __forceinline__ unsigned long long packhf(unsigned tag, float v) {
    return ((unsigned long long)tag << 32) | (unsigned long long)__float_as_uint(v);
}
__device__ __forceinline__ float tanh_fast(float x) {
    return 1.f - 2.f / (__expf(2.f * x) + 1.f);
}
__device__ __forceinline__ float sigm_fast(float x) {
    return 1.f / (1.f + __expf(-x));
}

// ---------------- init: seed h0 pairs (tag 0), poison other parity ----------------
__global__ void init_kernel(const float* __restrict__ h0) {
    int tid = threadIdx.x;                // 1024 threads
    int dir = tid >> 9, i = tid & 511;
    g_hpair[dir][0][i] = packhf(0u, h0[dir * HID + i]);
    g_hpair[dir][1][i] = packhf(0x7fffffffu, 0.f);
}

// ---------------- K1: x_proj = emb(gather) @ w_ih^T + b_ih + b_hh ----------------
__global__ __launch_bounds__(256) void xproj_kernel(
    const int*   __restrict__ sentence,
    const float* __restrict__ embed,
    const float* __restrict__ w_ih_f, const float* __restrict__ b_ih_f, const float* __restrict__ b_hh_f,
    const float* __restrict__ w_ih_b, const float* __restrict__ b_ih_b, const float* __restrict__ b_hh_b)
{
    const int dir = blockIdx.z;
    const float* __restrict__ w_ih = dir ? w_ih_b : w_ih_f;
    const float* __restrict__ bi   = dir ? b_ih_b : b_ih_f;
    const float* __restrict__ bh   = dir ? b_hh_b : b_hh_f;

    const int j0 = blockIdx.x * 64;
    const int t0 = blockIdx.y * 64;

    __shared__ __align__(16) float As[8][64];
    __shared__ __align__(16) float Bs[8][64];
    __shared__ int sidx[64];

    const int tid = threadIdx.x;
    if (tid < 64) {
        int t = t0 + tid;
        sidx[tid] = sentence[dir ? (T_LEN - 1 - t) : t];
    }
    __syncthreads();

    const int tx = tid & 15, ty = tid >> 4;
    const int lr = tid >> 2;
    const int le = (tid & 3) * 2;

    float acc[4][4] = {};

    for (int e0 = 0; e0 < EMBD; e0 += 8) {
        const float* arow = embed + (size_t)sidx[lr] * EMBD;
        const float* brow = w_ih + (size_t)(j0 + lr) * EMBD;
        int e = e0 + le;
        As[le][lr]     = (e     < EMBD) ? arow[e]     : 0.f;
        As[le + 1][lr] = (e + 1 < EMBD) ? arow[e + 1] : 0.f;
        Bs[le][lr]     = (e     < EMBD) ? brow[e]     : 0.f;
        Bs[le + 1][lr] = (e + 1 < EMBD) ? brow[e + 1] : 0.f;
        __syncthreads();
#pragma unroll
        for (int kk = 0; kk < 8; kk++) {
            float4 a = *(const float4*)&As[kk][ty * 4];
            float4 b = *(const float4*)&Bs[kk][tx * 4];
            float av[4] = {a.x, a.y, a.z, a.w};
            float bv[4] = {b.x, b.y, b.z, b.w};
#pragma unroll
            for (int i = 0; i < 4; i++)
#pragma unroll
                for (int j = 0; j < 4; j++)
                    acc[i][j] = fmaf(av[i], bv[j], acc[i][j]);
        }
        __syncthreads();
    }

#pragma unroll
    for (int i = 0; i < 4; i++) {
        int t = t0 + ty * 4 + i;
#pragma unroll
        for (int j = 0; j < 4; j++) {
            int jj = j0 + tx * 4 + j;
            g_xproj[dir][t][jj] = acc[i][j] + bi[jj] + bh[jj];
        }
    }
}

// ---------------- K3: persistent BiLSTM, BOTH directions per CTA ----------------
// 64 CTAs. Warp w owns h-index hidx=cid*8+w for dir0 AND dir1.
// Lane = gate*8+kg. One poll phase + one barrier per step; compute of one
// direction hides the publish latency of the other.
__global__ __launch_bounds__(256, 1) void lstm_kernel(
    const float* __restrict__ w_hh_f,
    const float* __restrict__ w_hh_b,
    const float* __restrict__ c0)
{
    const int cid  = blockIdx.x;
    const int tid  = threadIdx.x;
    const int wid  = tid >> 5;
    const int lane = tid & 31;
    const int gate = lane >> 3;
    const int kg   = lane & 7;
    const int hidx = cid * 8 + wid;
    const int row  = gate * HID + hidx;

    // weights for both dirs, swizzled so smem reads rotate by kg (conflict-free)
    float4 wA[16], wB[16];
    {
        const float4* ra = (const float4*)(w_hh_f + (size_t)row * HID + kg * 64);
        const float4* rb = (const float4*)(w_hh_b + (size_t)row * HID + kg * 64);
#pragma unroll
        for (int kk = 0; kk < 16; kk++) {
            wA[kk] = ra[(kk + kg) & 15];
            wB[kk] = rb[(kk + kg) & 15];
        }
    }

    __shared__ __align__(16) float h_shA[2][HID];
    __shared__ __align__(16) float h_shB[2][HID];

    float cA = (lane == 0) ? c0[hidx]       : 0.f;
    float cB = (lane == 0) ? c0[HID + hidx] : 0.f;
    float xpA = (kg == 0) ? g_xproj[0][0][row] : 0.f;
    float xpB = (kg == 0) ? g_xproj[1][0][row] : 0.f;

    for (int t = 0; t < T_LEN; t++) {
        const int p = t & 1;
        // --- poll both dirs' h(t): 2 words each, stash to smem ---
        {
            const unsigned long long* pa = g_hpair[0][p] + 2 * tid;
            const unsigned long long* pb = g_hpair[1][p] + 2 * tid;
            const unsigned wanted = (unsigned)t;
            unsigned long long a0, a1;
            do {
                asm volatile("ld.relaxed.gpu.global.v2.u64 {%0,%1}, [%2];"
                             : "=l"(a0), "=l"(a1) : "l"(pa) : "memory");
            } while ((unsigned)(a0 >> 32) != wanted || (unsigned)(a1 >> 32) != wanted);
            unsigned long long b0, b1;
            do {
                asm volatile("ld.relaxed.gpu.global.v2.u64 {%0,%1}, [%2];"
                             : "=l"(b0), "=l"(b1) : "l"(pb) : "memory");
            } while ((unsigned)(b0 >> 32) != wanted || (unsigned)(b1 >> 32) != wanted);
            h_shA[p][2 * tid]     = __uint_as_float((unsigned)a0);
            h_shA[p][2 * tid + 1] = __uint_as_float((unsigned)a1);
            h_shB[p][2 * tid]     = __uint_as_float((unsigned)b0);
            h_shB[p][2 * tid + 1] = __uint_as_float((unsigned)b1);
        }
        __syncthreads();

        // ================= direction 0 =================
        {
            float a0 = (kg == 0) ? xpA : 0.f, a1 = 0.f;
            const float* hb = h_shA[p] + kg * 64;
#pragma unroll
            for (int kk = 0; kk < 16; kk++) {
                float4 h4 = *(const float4*)(hb + (((kk + kg) & 15) << 2));
                a0 = fmaf(wA[kk].x, h4.x, a0);
                a1 = fmaf(wA[kk].y, h4.y, a1);
                a0 = fmaf(wA[kk].z, h4.z, a0);
                a1 = fmaf(wA[kk].w, h4.w, a1);
            }
            float acc = a0 + a1;
            acc += __shfl_xor_sync(0xffffffffu, acc, 4);
            acc += __shfl_xor_sync(0xffffffffu, acc, 2);
            acc += __shfl_xor_sync(0xffffffffu, acc, 1);
            float vf = __shfl_sync(0xffffffffu, acc, 8);
            float vg = __shfl_sync(0xffffffffu, acc, 16);
            float vo = __shfl_sync(0xffffffffu, acc, 24);
            if (lane == 0) {
                float fi = sigm_fast(acc);
                float ff = sigm_fast(vf);
                float fo = sigm_fast(vo);
                cA = ff * cA + fi * tanh_fast(vg);
                float hn = fo * tanh_fast(cA);
                unsigned long long* wp = g_hpair[0][p ^ 1] + hidx;
                unsigned long long pv = packhf((unsigned)(t + 1), hn);
                asm volatile("st.relaxed.gpu.global.u64 [%0], %1;" :: "l"(wp), "l"(pv) : "memory");
                g_hs[0][t][hidx] = hn;
            }
            if (kg == 0 && t + 1 < T_LEN) xpA = g_xproj[0][t + 1][row];
        }
        // ================= direction 1 =================
        {
            float a0 = (kg == 0) ? xpB : 0.f, a1 = 0.f;
            const float* hb = h_shB[p] + kg * 64;
#pragma unroll
            for (int kk = 0; kk < 16; kk++) {
                float4 h4 = *(const float4*)(hb + (((kk + kg) & 15) << 2));
                a0 = fmaf(wB[kk].x, h4.x, a0);
                a1 = fmaf(wB[kk].y, h4.y, a1);
                a0 = fmaf(wB[kk].z, h4.z, a0);
                a1 = fmaf(wB[kk].w, h4.w, a1);
            }
            float acc = a0 + a1;
            acc += __shfl_xor_sync(0xffffffffu, acc, 4);
            acc += __shfl_xor_sync(0xffffffffu, acc, 2);
            acc += __shfl_xor_sync(0xffffffffu, acc, 1);
            float vf = __shfl_sync(0xffffffffu, acc, 8);
            float vg = __shfl_sync(0xffffffffu, acc, 16);
            float vo = __shfl_sync(0xffffffffu, acc, 24);
            if (lane == 0) {
                float fi = sigm_fast(acc);
                float ff = sigm_fast(vf);
                float fo = sigm_fast(vo);
                cB = ff * cB + fi * tanh_fast(vg);
                float hn = fo * tanh_fast(cB);
                unsigned long long* wp = g_hpair[1][p ^ 1] + hidx;
                unsigned long long pv = packhf((unsigned)(t + 1), hn);
                asm volatile("st.relaxed.gpu.global.u64 [%0], %1;" :: "l"(wp), "l"(pv) : "memory");
                g_hs[1][t][hidx] = hn;
            }
            if (kg == 0 && t + 1 < T_LEN) xpB = g_xproj[1][t + 1][row];
        }
        // no trailing barrier: next stash writes the other parity buffers;
        // reuse of this parity is gated by the NEXT iteration's barrier.
    }
}

// ---------------- K4: feats[t,k] = [h_f(t), h_b(t)] . W_tag[k] + b_tag[k] ----------------
__global__ __launch_bounds__(256) void feats_kernel(
    const float* __restrict__ W_tag, const float* __restrict__ b_tag)
{
    const int t = blockIdx.x;
    __shared__ float hsm[2 * HID];
    const int tid = threadIdx.x;
    for (int i = tid; i < HID; i += 256) {
        hsm[i]       = g_hs[0][t][i];
        hsm[HID + i] = g_hs[1][T_LEN - 1 - t][i];
    }
    __syncthreads();
    const int wid = tid >> 5, lane = tid & 31;
    for (int k = wid; k < KTAG; k += 8) {
        const float* wrow = W_tag + (size_t)k * (2 * HID);
        float s = 0.f;
#pragma unroll
        for (int m = 0; m < 32; m++)
            s = fmaf(wrow[m * 32 + lane], hsm[m * 32 + lane], s);
#pragma unroll
        for (int off = 16; off; off >>= 1)
            s += __shfl_xor_sync(0xffffffffu, s, off);
        if (lane == 0) g_feats[t][k] = s + b_tag[k];
    }
}

// ---------------- K5a: per-chunk sequential composition (256 warps) ----------------
__global__ __launch_bounds__(32) void crf_chunk_kernel(const float* __restrict__ trans)
{
    const int c = blockIdx.x;
    const int lane = threadIdx.x;
    __shared__ float Tsm[KTAG][KTAG];
    __shared__ float Mbuf[2][KTAG][KTAG];
    __shared__ float fsm[KTAG];

    for (int i = lane; i < KTAG * KTAG; i += 32)
        Tsm[i / KTAG][i % KTAG] = trans[i];
    __syncwarp();

    if (lane < KTAG) fsm[lane] = g_feats[c * CHUNK][lane];
    __syncwarp();
    for (int e = lane; e < KTAG * KTAG; e += 32)
        Mbuf[0][e / KTAG][e % KTAG] = Tsm[e / KTAG][e % KTAG] + fsm[e / KTAG];
    __syncwarp();

    int cur = 0;
    for (int s = 1; s < CHUNK; s++) {
        if (lane < KTAG) fsm[lane] = g_feats[c * CHUNK + s][lane];
        __syncwarp();
        for (int e = lane; e < KTAG * KTAG; e += 32) {
            int j = e / KTAG, i = e % KTAG;
            float v[KTAG], mx = -3.4e38f;
#pragma unroll
            for (int k = 0; k < KTAG; k++) {
                v[k] = Tsm[j][k] + Mbuf[cur][k][i];
                mx = fmaxf(mx, v[k]);
            }
            float sm = 0.f;
#pragma unroll
            for (int k = 0; k < KTAG; k++) sm += __expf(v[k] - mx);
            Mbuf[cur ^ 1][j][i] = fsm[j] + mx + __logf(sm);
        }
        __syncwarp();
        cur ^= 1;
    }
    for (int e = lane; e < KTAG * KTAG; e += 32)
        g_tree[0][c][e / KTAG][e % KTAG] = Mbuf[cur][e / KTAG][e % KTAG];
}

// ---------------- K5b: tree combine. out[b] = in[2b+1] (.) in[2b] ----------------
__global__ __launch_bounds__(32) void crf_combine_kernel(int s)
{
    const int b = blockIdx.x;
    const int lane = threadIdx.x;
    const float (*in)[KTAG][KTAG]  = g_tree[s & 1];
    float (*out)[KTAG][KTAG]       = g_tree[(s & 1) ^ 1];
    __shared__ float Lo[KTAG][KTAG], Hi[KTAG][KTAG];
    for (int i = lane; i < KTAG * KTAG; i += 32) {
        Lo[i / KTAG][i % KTAG] = in[2 * b][i / KTAG][i % KTAG];
        Hi[i / KTAG][i % KTAG] = in[2 * b + 1][i / KTAG][i % KTAG];
    }
    __syncwarp();
    for (int e = lane; e < KTAG * KTAG; e += 32) {
        int j = e / KTAG, i = e % KTAG;
        float v[KTAG], mx = -3.4e38f;
#pragma unroll
        for (int k = 0; k < KTAG; k++) {
            v[k] = Hi[j][k] + Lo[k][i];
            mx = fmaxf(mx, v[k]);
        }
        float sm = 0.f;
#pragma unroll
        for (int k = 0; k < KTAG; k++) sm += __expf(v[k] - mx);
        out[b][j][i] = mx + __logf(sm);
    }
}

// ---------------- K5c: final score = forward - gold ----------------
__global__ void crf_final_kernel(const int* __restrict__ tags,
                                 const float* __restrict__ trans,
                                 float* __restrict__ out)
{
    __shared__ float partial[128];
    const int tid = threadIdx.x;

    float loc = 0.f;
    for (int t = tid; t < T_LEN; t += 128) {
        int tg = tags[t];
        int pv = t ? tags[t - 1] : START_TAG;
        loc += trans[tg * KTAG + pv] + g_feats[t][tg];
    }
    partial[tid] = loc;
    __syncthreads();

    if (tid == 0) {
        float gold = trans[STOP_TAG * KTAG + tags[T_LEN - 1]];
        for (int i = 0; i < 128; i++) gold += partial[i];

        const float (*C)[KTAG] = g_tree[0][0];
        float alpha[KTAG];
        for (int j = 0; j < KTAG; j++) {
            float mx = -3.4e38f, v[KTAG];
            for (int i = 0; i < KTAG; i++) {
                v[i] = C[j][i] + ((i == START_TAG) ? 0.f : NEGV);
                mx = fmaxf(mx, v[i]);
            }
            float sm = 0.f;
            for (int i = 0; i < KTAG; i++) sm += __expf(v[i] - mx);
            alpha[j] = mx + __logf(sm);
        }
        float mx = -3.4e38f;
        for (int j = 0; j < KTAG; j++)
            mx = fmaxf(mx, alpha[j] + trans[STOP_TAG * KTAG + j]);
        float sm = 0.f;
        for (int j = 0; j < KTAG; j++)
            sm += __expf(alpha[j] + trans[STOP_TAG * KTAG + j] - mx);
        out[0] = (mx + __logf(sm)) - gold;
    }
}

// ---------------- launch ----------------
extern "C" void kernel_launch(void* const* d_in, const int* in_sizes, int n_in,
                              void* d_out, int out_size)
{
    const int*   sentence = (const int*)d_in[0];
    const int*   tags     = (const int*)d_in[1];
    const float* embed    = (const float*)d_in[2];
    const float* w_ih_f   = (const float*)d_in[3];
    const float* w_hh_f   = (const float*)d_in[4];
    const float* b_ih_f   = (const float*)d_in[5];
    const float* b_hh_f   = (const float*)d_in[6];
    const float* w_ih_b   = (const float*)d_in[7];
    const float* w_hh_b   = (const float*)d_in[8];
    const float* b_ih_b   = (const float*)d_in[9];
    const float* b_hh_b   = (const float*)d_in[10];
    const float* h0       = (const float*)d_in[11];
    const float* c0       = (const float*)d_in[12];
    const float* W_tag    = (const float*)d_in[13];
    const float* b_tag    = (const float*)d_in[14];
    const float* trans    = (const float*)d_in[15];

    init_kernel<<<1, 1024>>>(h0);

    dim3 g1((4 * HID) / 64, T_LEN / 64, 2);
    xproj_kernel<<<g1, 256>>>(sentence, embed,
                              w_ih_f, b_ih_f, b_hh_f,
                              w_ih_b, b_ih_b, b_hh_b);

    lstm_kernel<<<64, 256>>>(w_hh_f, w_hh_b, c0);

    feats_kernel<<<T_LEN, 256>>>(W_tag, b_tag);

    crf_chunk_kernel<<<NCHUNK, 32>>>(trans);
    for (int s = 0; s < 8; s++)
        crf_combine_kernel<<<(NCHUNK / 2) >> s, 32>>>(s);
    crf_final_kernel<<<1, 128>>>(tags, trans, (float*)d_out);
}